// round 15
// baseline (speedup 1.0000x reference)
#include <cuda_runtime.h>
#include <cstdint>
#include <cstddef>

// ---------------------------------------------------------------------------
// 2-layer GraphSAGE mean-aggregator + segment sum + SELU readout.
//
// R15 = R10 (proven 166.6us) with the readout kernel FUSED into k2b via the
// last-block pattern:
//  K1u: (R10 exact) unified warp-specialized persistent kernel, grid 148.
//  K2b: (R10 exact GEMM+atomics) + after seg atomics, threadfence + ticket;
//       the last CTA to finish runs the full 64-graph readout MLP from smem.
// ---------------------------------------------------------------------------

static constexpr int NN  = 10000;
static constexpr int DIM = 64;
static constexpr int G   = 64;

__device__ float g_ma12[NN * 128];
__device__ float g_a01 [NN * 128];
__device__ float g_seg [G * 128];
__device__ unsigned g_done = 0;   // monotonic ticket counter (replay-safe)

// ---------------------------------------------------------------------------
__device__ __forceinline__ void fma2(unsigned long long& a,
                                     unsigned long long x, unsigned long long w) {
    asm("fma.rn.f32x2 %0, %1, %2, %3;" : "=l"(a) : "l"(x), "l"(w), "l"(a));
}
__device__ __forceinline__ void fadd2(unsigned long long& a, unsigned long long b) {
    asm("add.rn.f32x2 %0, %1, %2;" : "=l"(a) : "l"(a), "l"(b));
}
__device__ __forceinline__ unsigned long long fmul2(unsigned long long a,
                                                    unsigned long long b) {
    unsigned long long r;
    asm("mul.rn.f32x2 %0, %1, %2;" : "=l"(r) : "l"(a), "l"(b));
    return r;
}
__device__ __forceinline__ unsigned long long pack2(float x) {
    unsigned long long r;
    asm("mov.b64 %0, {%1, %1};" : "=l"(r) : "f"(x));
    return r;
}
__device__ __forceinline__ void unpack2(unsigned long long v, float& lo, float& hi) {
    asm("mov.b64 {%0, %1}, %2;" : "=f"(lo), "=f"(hi) : "l"(v));
}
__device__ __forceinline__ float selu_f(float x) {
    const float SC = 1.0507009873554805f;
    const float AL = 1.6732632423543772f;
    return SC * (x > 0.0f ? x : AL * (expf(x) - 1.0f));
}

// ---- mbarrier helpers ----
__device__ __forceinline__ uint32_t smem_u32(const void* p) {
    uint32_t a;
    asm("{ .reg .u64 t; cvta.to.shared.u64 t, %1; cvt.u32.u64 %0, t; }"
        : "=r"(a) : "l"(p));
    return a;
}
__device__ __forceinline__ void mbar_init(uint32_t addr, uint32_t count) {
    asm volatile("mbarrier.init.shared.b64 [%0], %1;" :: "r"(addr), "r"(count)
                 : "memory");
}
__device__ __forceinline__ void mbar_arrive(uint32_t addr) {
    asm volatile("mbarrier.arrive.shared.b64 _, [%0];" :: "r"(addr) : "memory");
}
__device__ __forceinline__ void mbar_wait(uint32_t addr, uint32_t parity) {
    asm volatile(
        "{\n\t"
        ".reg .pred P1;\n\t"
        "WAIT_LOOP_%=:\n\t"
        "mbarrier.try_wait.parity.acquire.cta.shared::cta.b64 P1, [%0], %1, 0x989680;\n\t"
        "@P1 bra.uni WAIT_DONE_%=;\n\t"
        "bra.uni WAIT_LOOP_%=;\n\t"
        "WAIT_DONE_%=:\n\t"
        "}"
        :: "r"(addr), "r"(parity) : "memory");
}

// One k-group (4 k) of the R-row x 8-col GEMM (cols tx*4.., 64+tx*4..).
template <int KP, int R>
__device__ __forceinline__ void kgroupR(const float* __restrict__ Xp,
                                        const float* __restrict__ WA,
                                        const float* __restrict__ WB,
                                        int g, unsigned long long (&acc2)[R][4]) {
    float4 x4[R];
#pragma unroll
    for (int r = 0; r < R; r++) x4[r] = *(const float4*)(Xp + r * KP + g * 4);
#pragma unroll
    for (int kk = 0; kk < 4; kk++) {
        ulonglong2 wa = *(const ulonglong2*)(WA + (g * 4 + kk) * 128);
        ulonglong2 wb = *(const ulonglong2*)(WB + (g * 4 + kk) * 128);
#pragma unroll
        for (int r = 0; r < R; r++) {
            float xs = kk == 0 ? x4[r].x : kk == 1 ? x4[r].y
                     : kk == 2 ? x4[r].z : x4[r].w;
            unsigned long long xx = pack2(xs);
            fma2(acc2[r][0], xx, wa.x);
            fma2(acc2[r][1], xx, wa.y);
            fma2(acc2[r][2], xx, wb.x);
            fma2(acc2[r][3], xx, wb.y);
        }
    }
}

template <int K, int KP, int R>
__device__ __forceinline__ void gemm_core(const float* __restrict__ Xs,
                                          const float* __restrict__ Ws,
                                          int tx, int ty,
                                          unsigned long long (&acc2)[R][4]) {
    const float* Xp = Xs + ty * R * KP;
    const float* WA = Ws + tx * 4;
    const float* WB = Ws + 64 + tx * 4;
#pragma unroll 4
    for (int g = 0; g < K / 4; g++) kgroupR<KP, R>(Xp, WA, WB, g, acc2);
}

// ---------------------------------------------------------------------------
// K1u: unified persistent WS kernel (R10 exact). grid 148, 640 thr.
// smem: Xs[3] 80x132 (126720 B) + Ws 128x128 (65536 B) + 6 mbarriers (48 B).
// ---------------------------------------------------------------------------
static constexpr int K1_SLOT  = 80 * 132;
static constexpr int K1_BAROF = (3 * K1_SLOT + 128 * 128) * 4;
static constexpr int NT_A12   = 1250;
static constexpr int NT_A01   = 125;
static constexpr int NT_TOT   = NT_A12 + NT_A01;

__global__ void __launch_bounds__(640, 1)
k1u(const float* __restrict__ h0, const float* __restrict__ h1,
    const float* __restrict__ h2,
    const float* __restrict__ w0, const float* __restrict__ b0,
    float* __restrict__ ma12, float* __restrict__ a01) {
    extern __shared__ float smem[];
    float* Ws = smem + 3 * K1_SLOT;

    const int tid = threadIdx.x;
    const bool prod = (tid >= 320);
    const uint32_t sb = smem_u32(smem);
    const uint32_t barf = sb + K1_BAROF;
    const uint32_t bare = sb + K1_BAROF + 24;

    if (blockIdx.x == 0) {
        for (int i = tid; i < G * 128; i += 640) g_seg[i] = 0.0f;
    }
    if (tid == 0) {
#pragma unroll
        for (int s = 0; s < 3; s++) {
            mbar_init(barf + s * 8, 320);
            mbar_init(bare + s * 8, 320);
        }
    }

    const int ptid = prod ? (tid - 320) : 0;
    int r_s[4], c_s[4];
#pragma unroll
    for (int s = 0; s < 4; s++) {
        int idx = ptid + s * 320;
        r_s[s] = idx >> 4;
        c_s[s] = (idx & 15) << 2;
    }

    const int tx = tid & 15, ty = tid >> 4;
    float bv[8];
    if (!prod) {
#pragma unroll
        for (int it = 0; it < 13; it++) {
            int i = tid + it * 320;
            if (i < 4096)
                *(float4*)(Ws + i * 4) = *(const float4*)(w0 + i * 4);
        }
#pragma unroll
        for (int j = 0; j < 4; j++) {
            bv[j]     = b0[tx * 4 + j];
            bv[4 + j] = b0[64 + tx * 4 + j];
        }
    }
    __syncthreads();

    const int nt = (NT_TOT - blockIdx.x + gridDim.x - 1) / gridDim.x;

    if (prod) {
        const unsigned long long s04 = pack2(0.04f);
        const unsigned long long s10 = pack2(0.1f);
        int stage = 0, phase = 1;
        for (int i = 0; i < nt; i++) {
            const int t = blockIdx.x + i * gridDim.x;
            mbar_wait(bare + stage * 8, (uint32_t)phase);
            float* Xn = smem + stage * K1_SLOT;

            if (t < NT_A12) {
                const int rb = t * 80;
                const float* h2b = h2 + (size_t)rb * 1600;
                unsigned long long m2[4][2];
#pragma unroll
                for (int s = 0; s < 4; s++) { m2[s][0] = 0ULL; m2[s][1] = 0ULL; }
#pragma unroll 5
                for (int j = 0; j < 25; j++) {
#pragma unroll
                    for (int s = 0; s < 4; s++) {
                        ulonglong2 u = *(const ulonglong2*)(h2b
                            + (size_t)r_s[s] * 1600 + c_s[s] + j * 64);
                        fadd2(m2[s][0], u.x);
                        fadd2(m2[s][1], u.y);
                    }
                }
#pragma unroll
                for (int s = 0; s < 4; s++) {
                    *(ulonglong2*)(Xn + r_s[s] * 132 + 64 + c_s[s]) =
                        make_ulonglong2(fmul2(m2[s][0], s04), fmul2(m2[s][1], s04));
                    *(float4*)(Xn + r_s[s] * 132 + c_s[s]) =
                        *(const float4*)(h1 + (size_t)(rb + r_s[s]) * 64 + c_s[s]);
                }
            } else {
                const int rb = (t - NT_A12) * 80;
                unsigned long long m1[4][2];
#pragma unroll
                for (int s = 0; s < 4; s++) { m1[s][0] = 0ULL; m1[s][1] = 0ULL; }
#pragma unroll
                for (int j = 0; j < 10; j++) {
#pragma unroll
                    for (int s = 0; s < 4; s++) {
                        ulonglong2 u = *(const ulonglong2*)(h1
                            + ((size_t)(rb + r_s[s]) * 10 + j) * 64 + c_s[s]);
                        fadd2(m1[s][0], u.x);
                        fadd2(m1[s][1], u.y);
                    }
                }
#pragma unroll
                for (int s = 0; s < 4; s++) {
                    *(ulonglong2*)(Xn + r_s[s] * 132 + 64 + c_s[s]) =
                        make_ulonglong2(fmul2(m1[s][0], s10), fmul2(m1[s][1], s10));
                    *(float4*)(Xn + r_s[s] * 132 + c_s[s]) =
                        *(const float4*)(h0 + (size_t)(rb + r_s[s]) * 64 + c_s[s]);
                }
            }
            mbar_arrive(barf + stage * 8);
            if (++stage == 3) { stage = 0; phase ^= 1; }
        }
    } else {
        int stage = 0, phase = 0;
        for (int i = 0; i < nt; i++) {
            const int t = blockIdx.x + i * gridDim.x;
            mbar_wait(barf + stage * 8, (uint32_t)phase);
            float* Xc = smem + stage * K1_SLOT;

            unsigned long long acc2[4][4];
#pragma unroll
            for (int r = 0; r < 4; r++)
#pragma unroll
                for (int p = 0; p < 4; p++) acc2[r][p] = 0ULL;

            gemm_core<128, 132, 4>(Xc, Ws, tx, ty, acc2);

            if (t < NT_A12) {
#pragma unroll
                for (int r = 0; r < 4; r++) {
                    float v[8];
#pragma unroll
                    for (int p = 0; p < 4; p++)
                        unpack2(acc2[r][p], v[2 * p], v[2 * p + 1]);
#pragma unroll
                    for (int j = 0; j < 8; j++) {
                        float q = v[j] + bv[j];
                        v[j] = q > 0.0f ? q : 0.0f;
                    }
                    float* dr = Xc + (ty * 4 + r) * 132;
                    *(float4*)(dr + tx * 4)      = make_float4(v[0], v[1], v[2], v[3]);
                    *(float4*)(dr + 64 + tx * 4) = make_float4(v[4], v[5], v[6], v[7]);
                }
                asm volatile("bar.sync 1, 320;" ::: "memory");

#pragma unroll
                for (int it = 0; it < 4; it++) {
                    int o = tid + it * 320;
                    if (o < 1024) {
                        int gl = o >> 7, c = o & 127;
                        float s = 0.0f;
#pragma unroll
                        for (int r2 = 0; r2 < 10; r2++)
                            s += Xc[(gl * 10 + r2) * 132 + c];
                        ma12[(size_t)(t * 8 + gl) * 128 + c] = s * 0.1f;
                    }
                }
                mbar_arrive(bare + stage * 8);
            } else {
                mbar_arrive(bare + stage * 8);
                const int rb = (t - NT_A12) * 80;
#pragma unroll
                for (int r = 0; r < 4; r++) {
                    float v[8];
#pragma unroll
                    for (int p = 0; p < 4; p++)
                        unpack2(acc2[r][p], v[2 * p], v[2 * p + 1]);
#pragma unroll
                    for (int j = 0; j < 8; j++) {
                        float q = v[j] + bv[j];
                        v[j] = q > 0.0f ? q : 0.0f;
                    }
                    float* dr = a01 + (size_t)(rb + ty * 4 + r) * 128;
                    *(float4*)(dr + tx * 4)      = make_float4(v[0], v[1], v[2], v[3]);
                    *(float4*)(dr + 64 + tx * 4) = make_float4(v[4], v[5], v[6], v[7]);
                }
            }
            if (++stage == 3) { stage = 0; phase ^= 1; }
        }
    }
}

// ---------------------------------------------------------------------------
// K2b+readout: R10-exact GEMM + seg atomics; then last-finishing CTA runs
// the full readout MLP. grid 125, 320 thr, smem 214272 B.
// ---------------------------------------------------------------------------
__global__ void __launch_bounds__(320)
k2b_fused(const float* __restrict__ a01, const float* __restrict__ ma12,
          const float* __restrict__ w1, const float* __restrict__ b1,
          const float* __restrict__ wr1, const float* __restrict__ br1,
          const float* __restrict__ wr2, const float* __restrict__ br2,
          const float* __restrict__ wr3, const float* __restrict__ br3,
          const int* __restrict__ gid, float* __restrict__ seg,
          float* __restrict__ outp, int n) {
    extern __shared__ float smem[];
    float* Xs = smem;               // 80 * 260
    float* Ws = smem + 80 * 260;    // 256 * 128

    const int tid = threadIdx.x;
    const int rb  = blockIdx.x * 80;

#pragma unroll
    for (int it = 0; it < 16; it++) {
        int i = tid + it * 320;
        int r = i >> 6, c = (i & 63) << 2;
        int row = rb + r;
        float4 v;
        if (c < 128) v = *(const float4*)(a01  + (size_t)row * 128 + c);
        else         v = *(const float4*)(ma12 + (size_t)row * 128 + c - 128);
        *(float4*)(Xs + r * 260 + c) = v;
    }
#pragma unroll
    for (int it = 0; it < 26; it++) {
        int i = tid + it * 320;
        if (i < 8192)
            *(float4*)(Ws + i * 4) = *(const float4*)(w1 + i * 4);
    }
    __syncthreads();

    const int tx = tid & 15, ty = tid >> 4;   // ty 0..19, R=4
    unsigned long long acc2[4][4];
#pragma unroll
    for (int r = 0; r < 4; r++)
#pragma unroll
        for (int p = 0; p < 4; p++) acc2[r][p] = 0ULL;
    gemm_core<256, 260, 4>(Xs, Ws, tx, ty, acc2);

    float bv[8];
#pragma unroll
    for (int j = 0; j < 4; j++) {
        bv[j]     = b1[tx * 4 + j];
        bv[4 + j] = b1[64 + tx * 4 + j];
    }
#pragma unroll
    for (int r = 0; r < 4; r++) {
        int row = rb + ty * 4 + r;
        if (row >= n) continue;
        float v[8];
#pragma unroll
        for (int p = 0; p < 4; p++) unpack2(acc2[r][p], v[2 * p], v[2 * p + 1]);
        int g = gid[row];
        float* sp = seg + (size_t)g * 128;
#pragma unroll
        for (int j = 0; j < 4; j++) {
            float q = v[j] + bv[j];
            atomicAdd(sp + tx * 4 + j, q > 0.0f ? q : 0.0f);
        }
#pragma unroll
        for (int j = 0; j < 4; j++) {
            float q = v[4 + j] + bv[4 + j];
            atomicAdd(sp + 64 + tx * 4 + j, q > 0.0f ? q : 0.0f);
        }
    }

    // ---- last-block readout ----
    __threadfence();               // seg atomics visible device-wide
    __syncthreads();               // all threads' atomics issued

    __shared__ unsigned s_last;
    if (tid == 0) {
        unsigned ticket = atomicAdd(&g_done, 1u);
        s_last = ((ticket % gridDim.x) == gridDim.x - 1u) ? 1u : 0u;
    }
    __syncthreads();
    if (!s_last) return;

    __threadfence();               // acquire: see all CTAs' seg atomics

    // smem layout for readout (reuse Xs region, all GEMM reads done)
    float* w1s  = Xs;              // 4480
    float* w2s  = Xs + 4480;       // 1225
    float* b1s  = Xs + 5705;       // 35
    float* b2s  = Xs + 5740;       // 35
    float* w3s  = Xs + 5775;       // 35
    float* segs = Xs + 5812;       // 8192 (64 x 128)
    float* r1s  = Xs + 14004;      // 2240 (64 x 35)
    float* r2s  = Xs + 16244;      // 2240

#pragma unroll
    for (int it = 0; it < 4; it++) {
        int i = tid + it * 320;
        if (i < 1120)
            *(float4*)(w1s + i * 4) = *(const float4*)(wr1 + i * 4);
    }
#pragma unroll
    for (int it = 0; it < 4; it++) {
        int i = tid + it * 320;
        if (i < 1225) w2s[i] = wr2[i];
    }
    if (tid < 35) { b1s[tid] = br1[tid]; b2s[tid] = br2[tid]; w3s[tid] = wr3[tid]; }
#pragma unroll
    for (int it = 0; it < 7; it++) {
        int i = tid + it * 320;
        if (i < 2048)
            *(float4*)(segs + i * 4) = *(const float4*)(seg + i * 4);
    }
    __syncthreads();

    // layer 1: 64 graphs x 35 outputs = 2240 items
#pragma unroll
    for (int it = 0; it < 7; it++) {
        int i = tid + it * 320;
        if (i < 2240) {
            int g = i / 35, j = i - g * 35;
            const float* s = segs + g * 128;
            float a0 = 0.f, a1 = 0.f, a2 = 0.f, a3 = 0.f;
#pragma unroll 8
            for (int k = 0; k < 128; k += 4) {
                a0 = fmaf(s[k],     w1s[(k)     * 35 + j], a0);
                a1 = fmaf(s[k + 1], w1s[(k + 1) * 35 + j], a1);
                a2 = fmaf(s[k + 2], w1s[(k + 2) * 35 + j], a2);
                a3 = fmaf(s[k + 3], w1s[(k + 3) * 35 + j], a3);
            }
            r1s[g * 35 + j] = selu_f((a0 + a1) + (a2 + a3) + b1s[j]);
        }
    }
    __syncthreads();

    // layer 2
#pragma unroll
    for (int it = 0; it < 7; it++) {
        int i = tid + it * 320;
        if (i < 2240) {
            int g = i / 35, j = i - g * 35;
            const float* rr = r1s + g * 35;
            float a0 = 0.f, a1 = 0.f;
#pragma unroll
            for (int k = 0; k < 34; k += 2) {
                a0 = fmaf(rr[k],     w2s[(k)     * 35 + j], a0);
                a1 = fmaf(rr[k + 1], w2s[(k + 1) * 35 + j], a1);
            }
            a0 = fmaf(rr[34], w2s[34 * 35 + j], a0);
            r2s[g * 35 + j] = selu_f(a0 + a1 + b2s[j]) * w3s[j];
        }
    }
    __syncthreads();

    // layer 3: one thread per graph
    if (tid < G) {
        float acc = br3[0];
        const float* rr = r2s + tid * 35;
#pragma unroll
        for (int j = 0; j < 35; j++) acc += rr[j];
        outp[tid] = acc;
    }
}

// ---------------------------------------------------------------------------
extern "C" void kernel_launch(void* const* d_in, const int* in_sizes, int n_in,
                              void* d_out, int out_size) {
    const float* h0  = (const float*)d_in[0];
    const float* h1  = (const float*)d_in[1];
    const float* h2  = (const float*)d_in[2];
    const float* w0  = (const float*)d_in[3];
    const float* b0  = (const float*)d_in[4];
    const float* w1  = (const float*)d_in[5];
    const float* b1  = (const float*)d_in[6];
    const float* wr1 = (const float*)d_in[7];
    const float* br1 = (const float*)d_in[8];
    const float* wr2 = (const float*)d_in[9];
    const float* br2 = (const float*)d_in[10];
    const float* wr3 = (const float*)d_in[11];
    const float* br3 = (const float*)d_in[12];
    const int*   gid = (const int*)d_in[13];

    const int n = in_sizes[0] / DIM;    // 10000

    float *ma12, *a01, *seg;
    cudaGetSymbolAddress((void**)&ma12, g_ma12);
    cudaGetSymbolAddress((void**)&a01,  g_a01);
    cudaGetSymbolAddress((void**)&seg,  g_seg);

    constexpr int SMEM_K1  = K1_BAROF + 48;                 // 192304
    constexpr int SMEM_K2B = (80 * 260 + 256 * 128) * 4;    // 214272
    cudaFuncSetAttribute((const void*)k1u,
                         cudaFuncAttributeMaxDynamicSharedMemorySize, SMEM_K1);
    cudaFuncSetAttribute((const void*)k2b_fused,
                         cudaFuncAttributeMaxDynamicSharedMemorySize, SMEM_K2B);

    // K1u: a12 + a01 tiles in one persistent launch (R10 exact); zeroes seg.
    k1u<<<148, 640, SMEM_K1>>>(h0, h1, h2, w0, b0, ma12, a01);

    // K2b: round-1 GEMM + fused segment-sum + last-block readout.
    k2b_fused<<<125, 320, SMEM_K2B>>>(a01, ma12, w1, b1,
                                      wr1, br1, wr2, br2, wr3, br3,
                                      gid, seg, (float*)d_out, n);
}

// round 16
// speedup vs baseline: 1.1679x; 1.1679x over previous
#include <cuda_runtime.h>
#include <cstdint>
#include <cstddef>

// ---------------------------------------------------------------------------
// 2-layer GraphSAGE mean-aggregator + segment sum + SELU readout.
//
// R16 = R10 exact (best measured: 166.6us).
//  K1u: unified warp-specialized persistent kernel (grid 148, 640 thr),
//       3-slot mbarrier ring. Work items 0..1374:
//         items <1250 : a12 tile  (producer: h1 + mean25(h2) [packed f32x2
//                       adds]; consumer: GEMM w0 + relu + mean10 -> ma12)
//         items >=1250: a01 tile  (producer: h0 + mean10(h1);
//                       consumer: same GEMM w0 + relu -> a01 gmem)
//  K2b: seg += relu([a01 | ma12] @ w1 + b1). 320 thr, 80 rows, R=4, grid 125.
//  K3 : readout MLP (one block/graph).
// ---------------------------------------------------------------------------

static constexpr int NN  = 10000;
static constexpr int DIM = 64;
static constexpr int G   = 64;

__device__ float g_ma12[NN * 128];
__device__ float g_a01 [NN * 128];
__device__ float g_seg [G * 128];

// ---------------------------------------------------------------------------
__device__ __forceinline__ void fma2(unsigned long long& a,
                                     unsigned long long x, unsigned long long w) {
    asm("fma.rn.f32x2 %0, %1, %2, %3;" : "=l"(a) : "l"(x), "l"(w), "l"(a));
}
__device__ __forceinline__ void fadd2(unsigned long long& a, unsigned long long b) {
    asm("add.rn.f32x2 %0, %1, %2;" : "=l"(a) : "l"(a), "l"(b));
}
__device__ __forceinline__ unsigned long long fmul2(unsigned long long a,
                                                    unsigned long long b) {
    unsigned long long r;
    asm("mul.rn.f32x2 %0, %1, %2;" : "=l"(r) : "l"(a), "l"(b));
    return r;
}
__device__ __forceinline__ unsigned long long pack2(float x) {
    unsigned long long r;
    asm("mov.b64 %0, {%1, %1};" : "=l"(r) : "f"(x));
    return r;
}
__device__ __forceinline__ void unpack2(unsigned long long v, float& lo, float& hi) {
    asm("mov.b64 {%0, %1}, %2;" : "=f"(lo), "=f"(hi) : "l"(v));
}

// ---- mbarrier helpers ----
__device__ __forceinline__ uint32_t smem_u32(const void* p) {
    uint32_t a;
    asm("{ .reg .u64 t; cvta.to.shared.u64 t, %1; cvt.u32.u64 %0, t; }"
        : "=r"(a) : "l"(p));
    return a;
}
__device__ __forceinline__ void mbar_init(uint32_t addr, uint32_t count) {
    asm volatile("mbarrier.init.shared.b64 [%0], %1;" :: "r"(addr), "r"(count)
                 : "memory");
}
__device__ __forceinline__ void mbar_arrive(uint32_t addr) {
    asm volatile("mbarrier.arrive.shared.b64 _, [%0];" :: "r"(addr) : "memory");
}
__device__ __forceinline__ void mbar_wait(uint32_t addr, uint32_t parity) {
    asm volatile(
        "{\n\t"
        ".reg .pred P1;\n\t"
        "WAIT_LOOP_%=:\n\t"
        "mbarrier.try_wait.parity.acquire.cta.shared::cta.b64 P1, [%0], %1, 0x989680;\n\t"
        "@P1 bra.uni WAIT_DONE_%=;\n\t"
        "bra.uni WAIT_LOOP_%=;\n\t"
        "WAIT_DONE_%=:\n\t"
        "}"
        :: "r"(addr), "r"(parity) : "memory");
}

// One k-group (4 k) of the R-row x 8-col GEMM (cols tx*4.., 64+tx*4..).
template <int KP, int R>
__device__ __forceinline__ void kgroupR(const float* __restrict__ Xp,
                                        const float* __restrict__ WA,
                                        const float* __restrict__ WB,
                                        int g, unsigned long long (&acc2)[R][4]) {
    float4 x4[R];
#pragma unroll
    for (int r = 0; r < R; r++) x4[r] = *(const float4*)(Xp + r * KP + g * 4);
#pragma unroll
    for (int kk = 0; kk < 4; kk++) {
        ulonglong2 wa = *(const ulonglong2*)(WA + (g * 4 + kk) * 128);
        ulonglong2 wb = *(const ulonglong2*)(WB + (g * 4 + kk) * 128);
#pragma unroll
        for (int r = 0; r < R; r++) {
            float xs = kk == 0 ? x4[r].x : kk == 1 ? x4[r].y
                     : kk == 2 ? x4[r].z : x4[r].w;
            unsigned long long xx = pack2(xs);
            fma2(acc2[r][0], xx, wa.x);
            fma2(acc2[r][1], xx, wa.y);
            fma2(acc2[r][2], xx, wb.x);
            fma2(acc2[r][3], xx, wb.y);
        }
    }
}

template <int K, int KP, int R>
__device__ __forceinline__ void gemm_core(const float* __restrict__ Xs,
                                          const float* __restrict__ Ws,
                                          int tx, int ty,
                                          unsigned long long (&acc2)[R][4]) {
    const float* Xp = Xs + ty * R * KP;
    const float* WA = Ws + tx * 4;
    const float* WB = Ws + 64 + tx * 4;
#pragma unroll 4
    for (int g = 0; g < K / 4; g++) kgroupR<KP, R>(Xp, WA, WB, g, acc2);
}

// ---------------------------------------------------------------------------
// K1u: unified persistent WS kernel. grid 148, 640 thr, 1 CTA/SM.
// smem: Xs[3] 80x132 (126720 B) + Ws 128x128 (65536 B) + 6 mbarriers (48 B).
// ---------------------------------------------------------------------------
static constexpr int K1_SLOT  = 80 * 132;
static constexpr int K1_BAROF = (3 * K1_SLOT + 128 * 128) * 4;
static constexpr int NT_A12   = 1250;   // 100000/80
static constexpr int NT_A01   = 125;    // 10000/80
static constexpr int NT_TOT   = NT_A12 + NT_A01;

__global__ void __launch_bounds__(640, 1)
k1u(const float* __restrict__ h0, const float* __restrict__ h1,
    const float* __restrict__ h2,
    const float* __restrict__ w0, const float* __restrict__ b0,
    float* __restrict__ ma12, float* __restrict__ a01) {
    extern __shared__ float smem[];
    float* Ws = smem + 3 * K1_SLOT;

    const int tid = threadIdx.x;
    const bool prod = (tid >= 320);
    const uint32_t sb = smem_u32(smem);
    const uint32_t barf = sb + K1_BAROF;
    const uint32_t bare = sb + K1_BAROF + 24;

    if (blockIdx.x == 0) {
        for (int i = tid; i < G * 128; i += 640) g_seg[i] = 0.0f;
    }
    if (tid == 0) {
#pragma unroll
        for (int s = 0; s < 3; s++) {
            mbar_init(barf + s * 8, 320);
            mbar_init(bare + s * 8, 320);
        }
    }

    // producer slot geometry
    const int ptid = prod ? (tid - 320) : 0;
    int r_s[4], c_s[4];
#pragma unroll
    for (int s = 0; s < 4; s++) {
        int idx = ptid + s * 320;
        r_s[s] = idx >> 4;
        c_s[s] = (idx & 15) << 2;
    }

    // consumer geometry + weights
    const int tx = tid & 15, ty = tid >> 4;   // consumers: ty 0..19
    float bv[8];
    if (!prod) {
#pragma unroll
        for (int it = 0; it < 13; it++) {
            int i = tid + it * 320;
            if (i < 4096)
                *(float4*)(Ws + i * 4) = *(const float4*)(w0 + i * 4);
        }
#pragma unroll
        for (int j = 0; j < 4; j++) {
            bv[j]     = b0[tx * 4 + j];
            bv[4 + j] = b0[64 + tx * 4 + j];
        }
    }
    __syncthreads();

    const int nt = (NT_TOT - blockIdx.x + gridDim.x - 1) / gridDim.x;

    if (prod) {
        const unsigned long long s04 = pack2(0.04f);
        const unsigned long long s10 = pack2(0.1f);
        int stage = 0, phase = 1;
        for (int i = 0; i < nt; i++) {
            const int t = blockIdx.x + i * gridDim.x;
            mbar_wait(bare + stage * 8, (uint32_t)phase);
            float* Xn = smem + stage * K1_SLOT;

            if (t < NT_A12) {
                // ---- a12 tile: h1 + mean25(h2), packed f32x2 adds ----
                const int rb = t * 80;
                const float* h2b = h2 + (size_t)rb * 1600;
                unsigned long long m2[4][2];
#pragma unroll
                for (int s = 0; s < 4; s++) { m2[s][0] = 0ULL; m2[s][1] = 0ULL; }
#pragma unroll 5
                for (int j = 0; j < 25; j++) {
#pragma unroll
                    for (int s = 0; s < 4; s++) {
                        ulonglong2 u = *(const ulonglong2*)(h2b
                            + (size_t)r_s[s] * 1600 + c_s[s] + j * 64);
                        fadd2(m2[s][0], u.x);
                        fadd2(m2[s][1], u.y);
                    }
                }
#pragma unroll
                for (int s = 0; s < 4; s++) {
                    *(ulonglong2*)(Xn + r_s[s] * 132 + 64 + c_s[s]) =
                        make_ulonglong2(fmul2(m2[s][0], s04), fmul2(m2[s][1], s04));
                    *(float4*)(Xn + r_s[s] * 132 + c_s[s]) =
                        *(const float4*)(h1 + (size_t)(rb + r_s[s]) * 64 + c_s[s]);
                }
            } else {
                // ---- a01 tile: h0 + mean10(h1) ----
                const int rb = (t - NT_A12) * 80;
                unsigned long long m1[4][2];
#pragma unroll
                for (int s = 0; s < 4; s++) { m1[s][0] = 0ULL; m1[s][1] = 0ULL; }
#pragma unroll
                for (int j = 0; j < 10; j++) {
#pragma unroll
                    for (int s = 0; s < 4; s++) {
                        ulonglong2 u = *(const ulonglong2*)(h1
                            + ((size_t)(rb + r_s[s]) * 10 + j) * 64 + c_s[s]);
                        fadd2(m1[s][0], u.x);
                        fadd2(m1[s][1], u.y);
                    }
                }
#pragma unroll
                for (int s = 0; s < 4; s++) {
                    *(ulonglong2*)(Xn + r_s[s] * 132 + 64 + c_s[s]) =
                        make_ulonglong2(fmul2(m1[s][0], s10), fmul2(m1[s][1], s10));
                    *(float4*)(Xn + r_s[s] * 132 + c_s[s]) =
                        *(const float4*)(h0 + (size_t)(rb + r_s[s]) * 64 + c_s[s]);
                }
            }
            mbar_arrive(barf + stage * 8);
            if (++stage == 3) { stage = 0; phase ^= 1; }
        }
    } else {
        int stage = 0, phase = 0;
        for (int i = 0; i < nt; i++) {
            const int t = blockIdx.x + i * gridDim.x;
            mbar_wait(barf + stage * 8, (uint32_t)phase);
            float* Xc = smem + stage * K1_SLOT;

            unsigned long long acc2[4][4];
#pragma unroll
            for (int r = 0; r < 4; r++)
#pragma unroll
                for (int p = 0; p < 4; p++) acc2[r][p] = 0ULL;

            gemm_core<128, 132, 4>(Xc, Ws, tx, ty, acc2);

            if (t < NT_A12) {
                // epilogue: bias + relu -> back into Xc, then mean10 -> ma12
#pragma unroll
                for (int r = 0; r < 4; r++) {
                    float v[8];
#pragma unroll
                    for (int p = 0; p < 4; p++)
                        unpack2(acc2[r][p], v[2 * p], v[2 * p + 1]);
#pragma unroll
                    for (int j = 0; j < 8; j++) {
                        float q = v[j] + bv[j];
                        v[j] = q > 0.0f ? q : 0.0f;
                    }
                    float* dr = Xc + (ty * 4 + r) * 132;
                    *(float4*)(dr + tx * 4)      = make_float4(v[0], v[1], v[2], v[3]);
                    *(float4*)(dr + 64 + tx * 4) = make_float4(v[4], v[5], v[6], v[7]);
                }
                asm volatile("bar.sync 1, 320;" ::: "memory");

#pragma unroll
                for (int it = 0; it < 4; it++) {
                    int o = tid + it * 320;
                    if (o < 1024) {
                        int gl = o >> 7, c = o & 127;
                        float s = 0.0f;
#pragma unroll
                        for (int r2 = 0; r2 < 10; r2++)
                            s += Xc[(gl * 10 + r2) * 132 + c];
                        ma12[(size_t)(t * 8 + gl) * 128 + c] = s * 0.1f;
                    }
                }
                mbar_arrive(bare + stage * 8);
            } else {
                // a01 epilogue: relu -> gmem directly; slot freed right away
                mbar_arrive(bare + stage * 8);
                const int rb = (t - NT_A12) * 80;
#pragma unroll
                for (int r = 0; r < 4; r++) {
                    float v[8];
#pragma unroll
                    for (int p = 0; p < 4; p++)
                        unpack2(acc2[r][p], v[2 * p], v[2 * p + 1]);
#pragma unroll
                    for (int j = 0; j < 8; j++) {
                        float q = v[j] + bv[j];
                        v[j] = q > 0.0f ? q : 0.0f;
                    }
                    float* dr = a01 + (size_t)(rb + ty * 4 + r) * 128;
                    *(float4*)(dr + tx * 4)      = make_float4(v[0], v[1], v[2], v[3]);
                    *(float4*)(dr + 64 + tx * 4) = make_float4(v[4], v[5], v[6], v[7]);
                }
            }
            if (++stage == 3) { stage = 0; phase ^= 1; }
        }
    }
}

// ---------------------------------------------------------------------------
// K2b: seg[g] += relu([a01 | ma12] @ w1 + b1). K=256, 80 rows, 320 thr (R=4),
// grid 125 (one wave). smem: Xs 80x260 + Ws 256x128 = 214272 B.
// ---------------------------------------------------------------------------
__global__ void __launch_bounds__(320)
k2b_fused(const float* __restrict__ a01, const float* __restrict__ ma12,
          const float* __restrict__ w1, const float* __restrict__ b1,
          const int* __restrict__ gid, float* __restrict__ seg, int n) {
    extern __shared__ float smem[];
    float* Xs = smem;               // 80 * 260
    float* Ws = smem + 80 * 260;    // 256 * 128

    const int tid = threadIdx.x;
    const int rb  = blockIdx.x * 80;

    // X staging: 80 rows x 64 float4 = 5120; 320 thr -> 16 unrolled rounds
#pragma unroll
    for (int it = 0; it < 16; it++) {
        int i = tid + it * 320;
        int r = i >> 6, c = (i & 63) << 2;
        int row = rb + r;
        float4 v;
        if (c < 128) v = *(const float4*)(a01  + (size_t)row * 128 + c);
        else         v = *(const float4*)(ma12 + (size_t)row * 128 + c - 128);
        *(float4*)(Xs + r * 260 + c) = v;
    }
    // W staging: 8192 float4; 320 thr -> 26 unrolled rounds (guarded)
#pragma unroll
    for (int it = 0; it < 26; it++) {
        int i = tid + it * 320;
        if (i < 8192)
            *(float4*)(Ws + i * 4) = *(const float4*)(w1 + i * 4);
    }
    __syncthreads();

    const int tx = tid & 15, ty = tid >> 4;   // ty 0..19, R=4
    unsigned long long acc2[4][4];
#pragma unroll
    for (int r = 0; r < 4; r++)
#pragma unroll
        for (int p = 0; p < 4; p++) acc2[r][p] = 0ULL;
    gemm_core<256, 260, 4>(Xs, Ws, tx, ty, acc2);

    float bv[8];
#pragma unroll
    for (int j = 0; j < 4; j++) {
        bv[j]     = b1[tx * 4 + j];
        bv[4 + j] = b1[64 + tx * 4 + j];
    }
#pragma unroll
    for (int r = 0; r < 4; r++) {
        int row = rb + ty * 4 + r;
        if (row >= n) continue;
        float v[8];
#pragma unroll
        for (int p = 0; p < 4; p++) unpack2(acc2[r][p], v[2 * p], v[2 * p + 1]);
        int g = gid[row];
        float* sp = seg + (size_t)g * 128;
#pragma unroll
        for (int j = 0; j < 4; j++) {
            float q = v[j] + bv[j];
            atomicAdd(sp + tx * 4 + j, q > 0.0f ? q : 0.0f);
        }
#pragma unroll
        for (int j = 0; j < 4; j++) {
            float q = v[4 + j] + bv[4 + j];
            atomicAdd(sp + 64 + tx * 4 + j, q > 0.0f ? q : 0.0f);
        }
    }
}

// ---------------------------------------------------------------------------
// Readout MLP: one block per graph (grid 64, 256 threads), unrolled staging.
// ---------------------------------------------------------------------------
__device__ __forceinline__ float selu_f(float x) {
    const float SC = 1.0507009873554805f;
    const float AL = 1.6732632423543772f;
    return SC * (x > 0.0f ? x : AL * (expf(x) - 1.0f));
}

__global__ void __launch_bounds__(256)
readout_kernel(const float* __restrict__ seg,
               const float* __restrict__ wr1, const float* __restrict__ br1,
               const float* __restrict__ wr2, const float* __restrict__ br2,
               const float* __restrict__ wr3, const float* __restrict__ br3,
               float* __restrict__ outp) {
    __shared__ float w1s[128 * 35];
    __shared__ float w2s[35 * 35];
    __shared__ float b1s[35], b2s[35], w3s[35];
    __shared__ float segs[128];
    __shared__ float r1s[35];
    __shared__ float r2s[35];

    const int tid = threadIdx.x;
    const int g   = blockIdx.x;

#pragma unroll
    for (int it = 0; it < 5; it++) {
        int i = tid + it * 256;
        if (i < 1120)
            *(float4*)(w1s + i * 4) = *(const float4*)(wr1 + i * 4);
    }
#pragma unroll
    for (int it = 0; it < 5; it++) {
        int i = tid + it * 256;
        if (i < 1225) w2s[i] = wr2[i];
    }
    if (tid < 35) { b1s[tid] = br1[tid]; b2s[tid] = br2[tid]; w3s[tid] = wr3[tid]; }
    if (tid < 128) segs[tid] = seg[g * 128 + tid];
    __syncthreads();

    if (tid < 35) {
        float a0 = 0.f, a1 = 0.f, a2 = 0.f, a3 = 0.f;
#pragma unroll 8
        for (int k = 0; k < 128; k += 4) {
            a0 = fmaf(segs[k],     w1s[(k)     * 35 + tid], a0);
            a1 = fmaf(segs[k + 1], w1s[(k + 1) * 35 + tid], a1);
            a2 = fmaf(segs[k + 2], w1s[(k + 2) * 35 + tid], a2);
            a3 = fmaf(segs[k + 3], w1s[(k + 3) * 35 + tid], a3);
        }
        r1s[tid] = selu_f((a0 + a1) + (a2 + a3) + b1s[tid]);
    }
    __syncthreads();

    if (tid < 35) {
        float a0 = 0.f, a1 = 0.f;
#pragma unroll
        for (int k = 0; k < 34; k += 2) {
            a0 = fmaf(r1s[k],     w2s[(k)     * 35 + tid], a0);
            a1 = fmaf(r1s[k + 1], w2s[(k + 1) * 35 + tid], a1);
        }
        a0 = fmaf(r1s[34], w2s[34 * 35 + tid], a0);
        r2s[tid] = selu_f(a0 + a1 + b2s[tid]) * w3s[tid];
    }
    __syncthreads();

    if (tid == 0) {
        float acc = br3[0];
#pragma unroll
        for (int j = 0; j < 35; j++) acc += r2s[j];
        outp[g] = acc;
    }
}

// ---------------------------------------------------------------------------
extern "C" void kernel_launch(void* const* d_in, const int* in_sizes, int n_in,
                              void* d_out, int out_size) {
    const float* h0  = (const float*)d_in[0];
    const float* h1  = (const float*)d_in[1];
    const float* h2  = (const float*)d_in[2];
    const float* w0  = (const float*)d_in[3];
    const float* b0  = (const float*)d_in[4];
    const float* w1  = (const float*)d_in[5];
    const float* b1  = (const float*)d_in[6];
    const float* wr1 = (const float*)d_in[7];
    const float* br1 = (const float*)d_in[8];
    const float* wr2 = (const float*)d_in[9];
    const float* br2 = (const float*)d_in[10];
    const float* wr3 = (const float*)d_in[11];
    const float* br3 = (const float*)d_in[12];
    const int*   gid = (const int*)d_in[13];

    const int n = in_sizes[0] / DIM;    // 10000

    float *ma12, *a01, *seg;
    cudaGetSymbolAddress((void**)&ma12, g_ma12);
    cudaGetSymbolAddress((void**)&a01,  g_a01);
    cudaGetSymbolAddress((void**)&seg,  g_seg);

    constexpr int SMEM_K1  = K1_BAROF + 48;                   // 192304
    constexpr int SMEM_K2B = (80 * 260 + 256 * 128) * 4;      // 214272
    cudaFuncSetAttribute((const void*)k1u,
                         cudaFuncAttributeMaxDynamicSharedMemorySize, SMEM_K1);
    cudaFuncSetAttribute((const void*)k2b_fused,
                         cudaFuncAttributeMaxDynamicSharedMemorySize, SMEM_K2B);

    // K1u: a12 tiles + a01 tiles in one persistent launch; also zeroes seg.
    k1u<<<148, 640, SMEM_K1>>>(h0, h1, h2, w0, b0, ma12, a01);

    // K2b: round-1 GEMM + fused segment-sum
    k2b_fused<<<125, 320, SMEM_K2B>>>(a01, ma12, w1, b1, gid, seg, n);

    // K3: readout
    readout_kernel<<<G, 256>>>(seg, wr1, br1, wr2, br2, wr3, br3, (float*)d_out);
}